// round 14
// baseline (speedup 1.0000x reference)
#include <cuda_runtime.h>
#include <math.h>

#define IN_C   32
#define OUT_C  64
#define HH     56
#define WWID   56
#define BB     4
#define TILE_H 8
#define TILE_W 8
#define PADH   (TILE_H + 2)          // 10
#define PADW   (TILE_W + 2)          // 10
#define NELEM  (PADH * PADW)         // 100
#define BST2   10                    // basis row stride in u64 (80 B: 16B-aligned, conflict-free)
#define NSPLIT 2
#define CCHUNK (IN_C / NSPLIT)       // 16
#define NOUT   (BB * OUT_C * HH * WWID)   // 802816

typedef unsigned long long u64;

__device__ __forceinline__ u64 dup2(float v) {
    unsigned u = __float_as_uint(v);
    return ((u64)u << 32) | (u64)u;
}
__device__ __forceinline__ void ffma2(u64& d, u64 a, u64 b) {
    asm("fma.rn.f32x2 %0, %1, %2, %0;" : "+l"(d) : "l"(a), "l"(b));
}

// One-time reorganized weights (device scratch; no allocation).
// g_ws[((c*9 + kk)*8 + f)*64 + o] = ws[o*2304 + (c*9+kk)*8 + f]
// g_wb[((c*9 + kk))*64 + o]       = wb[o*288 + c*9 + kk]
__device__ float g_ws[IN_C * 9 * 8 * OUT_C];
__device__ float g_wb[IN_C * 9 * OUT_C];
// Partial sums: [split][b][o][h][w]
__device__ float g_partS[NSPLIT * NOUT];
__device__ float g_partB[NSPLIT * NOUT];

__global__ __launch_bounds__(256)
void kan_reorg_kernel(const float* __restrict__ ws, const float* __restrict__ wb)
{
    const int idx = blockIdx.x * blockDim.x + threadIdx.x;
    if (idx < IN_C * 9 * 8 * OUT_C) {
        const int o = idx & 63;
        const int f = (idx >> 6) & 7;
        const int r = idx >> 9;            // c*9 + kk
        g_ws[idx] = ws[o * 2304 + r * 8 + f];
    }
    if (idx < IN_C * 9 * OUT_C) {
        const int o = idx & 63;
        const int r = idx >> 6;            // c*9 + kk
        g_wb[idx] = wb[o * 288 + r];
    }
}

__global__ __launch_bounds__(128)
void kan_partial_kernel(const float* __restrict__ x)
{
    __shared__ __align__(16) u64   s_b2[NELEM * BST2];    // [pix][f<8 dup'd bases; 8: dup'd x]
    __shared__ __align__(16) float s_ws[9 * 8 * OUT_C];   // [kk][f][o]
    __shared__ __align__(16) float s_wb[9 * OUT_C];       // [kk][o]

    const int tid   = threadIdx.x;
    const int og    = tid >> 3;     // 0..15 -> out channels og*4..og*4+3
    const int pg    = tid & 7;      // 0..7  -> output column within tile
    const int tw0   = blockIdx.x * TILE_W;
    const int th0   = blockIdx.y * TILE_H;
    const int b     = blockIdx.z >> 1;
    const int split = blockIdx.z & 1;
    const int c0    = split * CCHUNK;

    // packed accumulators: [op][p], lanes = channels og*4+2op (+0 low, +1 high)
    u64 accS2[2][TILE_H];
    u64 accB2[2][TILE_H];
    #pragma unroll
    for (int op = 0; op < 2; op++)
        #pragma unroll
        for (int p = 0; p < TILE_H; p++) { accS2[op][p] = 0ull; accB2[op][p] = 0ull; }

    #pragma unroll 1
    for (int ci = 0; ci < CCHUNK; ++ci) {
        const int c = c0 + ci;
        __syncthreads();   // protect smem from previous iteration's readers

        // ---- stage x tile, compute B-spline bases, store DUPLICATED (v,v) u64 ----
        if (tid < NELEM) {
            const int rr = tid / PADW;
            const int cc = tid - rr * PADW;
            const int gh = th0 - 1 + rr;
            const int gw = tw0 - 1 + cc;
            float v = 0.f;
            if (gh >= 0 && gh < HH && gw >= 0 && gw < WWID)
                v = x[(((b * IN_C) + c) * HH + gh) * WWID + gw];

            u64* bp = &s_b2[tid * BST2];
            #pragma unroll
            for (int f = 0; f < 8; f++) bp[f] = 0ull;
            bp[8] = dup2(v);

            // uniform cubic B-spline, knots t_i = -2.2 + 0.4*i ; s = 2.5v + 5.5
            const float s  = fmaf(v, 2.5f, 5.5f);
            const float fj = floorf(s);
            const int   j  = (int)fj;
            if (j >= 0 && j <= 10) {
                const float u   = s - fj;
                const float u2  = u * u;
                const float u3  = u2 * u;
                const float omu = 1.f - u;
                const float w0 = omu * omu * omu * (1.f / 6.f);
                const float w1 = (3.f * u3 - 6.f * u2 + 4.f) * (1.f / 6.f);
                const float w2 = (-3.f * u3 + 3.f * u2 + 3.f * u + 1.f) * (1.f / 6.f);
                const float w3 = u3 * (1.f / 6.f);
                const int i0 = j - 3;               // nonzero bases i0..i0+3, clip to [0,7]
                if (i0 >= 0)             bp[i0]     = dup2(w0);
                if (i0 >= -1 && i0 <= 6) bp[i0 + 1] = dup2(w1);
                if (i0 >= -2 && i0 <= 5) bp[i0 + 2] = dup2(w2);
                if (i0 <= 4)             bp[i0 + 3] = dup2(w3);
            }
        }

        // ---- stage weights for this input channel: contiguous vec4 copy ----
        {
            const float4* src = (const float4*)&g_ws[c * (9 * 8 * OUT_C)];
            float4*       dst = (float4*)s_ws;
            #pragma unroll
            for (int l = 0; l < 9; l++)
                dst[l * 128 + tid] = src[l * 128 + tid];

            const float4* srcb = (const float4*)&g_wb[c * (9 * OUT_C)];
            float4*       dstb = (float4*)s_wb;
            dstb[tid] = srcb[tid];
            if (tid < 16) dstb[128 + tid] = srcb[128 + tid];
        }
        __syncthreads();

        // ---- accumulate over the 3x3 taps (R12 structure, FMA2 inner) ----
        #pragma unroll 1
        for (int kh = 0; kh < 3; ++kh) {
            #pragma unroll 1
            for (int kw = 0; kw < 3; ++kw) {
                const int kk = kh * 3 + kw;

                // weights: float4 over o at this og; reinterpret as 2 packed u64
                const float* wsk = &s_ws[kk * 8 * OUT_C];
                float4 wv4[8];
                #pragma unroll
                for (int f = 0; f < 8; f++)
                    wv4[f] = *(const float4*)&wsk[f * OUT_C + (og << 2)];
                const u64* wp = reinterpret_cast<const u64*>(wv4);   // [f*2 + op]
                const float4 wb4 = *(const float4*)&s_wb[kk * OUT_C + (og << 2)];
                const u64* wbp = reinterpret_cast<const u64*>(&wb4); // [op]

                #pragma unroll
                for (int p = 0; p < TILE_H; p++) {
                    const int idx = (p + kh) * PADW + pg + kw;
                    const u64* bb = &s_b2[idx * BST2];
                    const ulonglong2 q0 = ((const ulonglong2*)bb)[0];
                    const ulonglong2 q1 = ((const ulonglong2*)bb)[1];
                    const ulonglong2 q2 = ((const ulonglong2*)bb)[2];
                    const ulonglong2 q3 = ((const ulonglong2*)bb)[3];
                    const u64 xd = bb[8];
                    const u64 bf2[8] = { q0.x, q0.y, q1.x, q1.y,
                                         q2.x, q2.y, q3.x, q3.y };
                    #pragma unroll
                    for (int op = 0; op < 2; op++) {
                        u64 t = accS2[op][p];
                        #pragma unroll
                        for (int f = 0; f < 8; f++)
                            ffma2(t, bf2[f], wp[f * 2 + op]);
                        accS2[op][p] = t;
                        ffma2(accB2[op][p], xd, wbp[op]);
                    }
                }
            }
        }
    }

    // ---- write raw partial sums (activation applied in combine) ----
    const int base = split * NOUT + b * (OUT_C * HH * WWID);
    #pragma unroll
    for (int op = 0; op < 2; op++) {
        const int o = (og << 2) + (op << 1);
        #pragma unroll
        for (int p = 0; p < TILE_H; p++) {
            const int idx = base + (o * HH + th0 + p) * WWID + tw0 + pg;
            const u64 vs = accS2[op][p];
            const u64 vb = accB2[op][p];
            g_partS[idx]             = __uint_as_float((unsigned)vs);
            g_partS[idx + HH * WWID] = __uint_as_float((unsigned)(vs >> 32));
            g_partB[idx]             = __uint_as_float((unsigned)vb);
            g_partB[idx + HH * WWID] = __uint_as_float((unsigned)(vb >> 32));
        }
    }
}

__global__ __launch_bounds__(256)
void kan_combine_kernel(const float* __restrict__ scaler, float* __restrict__ out)
{
    const int v = blockIdx.x * blockDim.x + threadIdx.x;   // float4 index
    if (v >= NOUT / 4) return;
    const int o = ((v * 4) / (HH * WWID)) & (OUT_C - 1);   // constant within a float4
    const float4 s0 = ((const float4*)g_partS)[v];
    const float4 s1 = ((const float4*)g_partS)[v + NOUT / 4];
    const float4 b0 = ((const float4*)g_partB)[v];
    const float4 b1 = ((const float4*)g_partB)[v + NOUT / 4];
    const float sc = scaler[o];
    float4 r;
    { const float zb = b0.x + b1.x; r.x = fmaf(sc, s0.x + s1.x, zb / (1.f + expf(-zb))); }
    { const float zb = b0.y + b1.y; r.y = fmaf(sc, s0.y + s1.y, zb / (1.f + expf(-zb))); }
    { const float zb = b0.z + b1.z; r.z = fmaf(sc, s0.z + s1.z, zb / (1.f + expf(-zb))); }
    { const float zb = b0.w + b1.w; r.w = fmaf(sc, s0.w + s1.w, zb / (1.f + expf(-zb))); }
    ((float4*)out)[v] = r;
}

extern "C" void kernel_launch(void* const* d_in, const int* in_sizes, int n_in,
                              void* d_out, int out_size)
{
    const float* x      = (const float*)d_in[0];
    const float* wb     = (const float*)d_in[1];
    const float* ws     = (const float*)d_in[2];
    const float* scaler = (const float*)d_in[3];
    float* out = (float*)d_out;

    kan_reorg_kernel<<<(IN_C * 9 * 8 * OUT_C + 255) / 256, 256>>>(ws, wb);

    dim3 grid(WWID / TILE_W, HH / TILE_H, BB * NSPLIT);   // (7, 7, 8) = 392 blocks
    kan_partial_kernel<<<grid, 128>>>(x);

    kan_combine_kernel<<<(NOUT / 4 + 255) / 256, 256>>>(scaler, out);
}

// round 15
// speedup vs baseline: 1.5660x; 1.5660x over previous
#include <cuda_runtime.h>
#include <math.h>

#define IN_C   32
#define OUT_C  64
#define HH     56
#define WWID   56
#define BB     4
#define TILE_H 8
#define TILE_W 8
#define PADH   (TILE_H + 2)          // 10
#define PADW   (TILE_W + 2)          // 10
#define NELEM  (PADH * PADW)         // 100
#define BSTRIDE 12                   // bases smem row stride (floats)
#define NSPLIT 3
#define NOUT   (BB * OUT_C * HH * WWID)   // 802816

// One-time reorganized weights (device scratch; no allocation).
// g_ws[((c*9 + kk)*8 + f)*64 + o] = ws[o*2304 + (c*9+kk)*8 + f]
// g_wb[((c*9 + kk))*64 + o]       = wb[o*288 + c*9 + kk]
__device__ float g_ws[IN_C * 9 * 8 * OUT_C];
__device__ float g_wb[IN_C * 9 * OUT_C];
// Partial sums: [split][b][o][h][w]
__device__ float g_partS[NSPLIT * NOUT];
__device__ float g_partB[NSPLIT * NOUT];

// thread = (o, r): read 8 contiguous floats of ws (one 32B sector), write
// 8 stores coalesced across threads (consecutive o at fixed (r,f)).
__global__ __launch_bounds__(256)
void kan_reorg_kernel(const float* __restrict__ ws, const float* __restrict__ wb)
{
    const int t = blockIdx.x * blockDim.x + threadIdx.x;   // 0 .. 64*288-1
    if (t >= OUT_C * IN_C * 9) return;
    const int o = t / (IN_C * 9);
    const int r = t - o * (IN_C * 9);      // c*9 + kk
    const float4 a = *(const float4*)&ws[o * 2304 + r * 8];
    const float4 bq = *(const float4*)&ws[o * 2304 + r * 8 + 4];
    g_ws[(r * 8 + 0) * OUT_C + o] = a.x;
    g_ws[(r * 8 + 1) * OUT_C + o] = a.y;
    g_ws[(r * 8 + 2) * OUT_C + o] = a.z;
    g_ws[(r * 8 + 3) * OUT_C + o] = a.w;
    g_ws[(r * 8 + 4) * OUT_C + o] = bq.x;
    g_ws[(r * 8 + 5) * OUT_C + o] = bq.y;
    g_ws[(r * 8 + 6) * OUT_C + o] = bq.z;
    g_ws[(r * 8 + 7) * OUT_C + o] = bq.w;
    g_wb[r * OUT_C + o] = wb[o * 288 + r];
}

__global__ __launch_bounds__(128)
void kan_partial_kernel(const float* __restrict__ x)
{
    __shared__ __align__(16) float s_x[NELEM];
    __shared__ __align__(16) float s_b[NELEM * BSTRIDE];
    __shared__ __align__(16) float s_ws[9 * 8 * OUT_C];   // [kk][f][o]
    __shared__ __align__(16) float s_wb[9 * OUT_C];       // [kk][o]

    const int tid   = threadIdx.x;
    const int og    = tid >> 3;     // 0..15 -> out channels og*4..og*4+3
    const int pg    = tid & 7;      // 0..7  -> output column within tile
    const int tw0   = blockIdx.x * TILE_W;
    const int th0   = blockIdx.y * TILE_H;
    const int b     = blockIdx.z / NSPLIT;
    const int split = blockIdx.z - b * NSPLIT;
    const int c0    = split * 11;                  // 0, 11, 22
    const int cn    = (split < 2) ? 11 : 10;       // 11, 11, 10

    float accS[4][TILE_H];   // [oi][p]
    float accB[4][TILE_H];
    #pragma unroll
    for (int i = 0; i < 4; i++)
        #pragma unroll
        for (int p = 0; p < TILE_H; p++) { accS[i][p] = 0.f; accB[i][p] = 0.f; }

    #pragma unroll 1
    for (int ci = 0; ci < cn; ++ci) {
        const int c = c0 + ci;
        __syncthreads();   // protect smem from previous iteration's readers

        // ---- stage x tile and compute B-spline bases (zero padding: bases(0) != 0) ----
        if (tid < NELEM) {
            const int rr = tid / PADW;
            const int cc = tid - rr * PADW;
            const int gh = th0 - 1 + rr;
            const int gw = tw0 - 1 + cc;
            float v = 0.f;
            if (gh >= 0 && gh < HH && gw >= 0 && gw < WWID)
                v = x[(((b * IN_C) + c) * HH + gh) * WWID + gw];
            s_x[tid] = v;

            float* bp = &s_b[tid * BSTRIDE];
            #pragma unroll
            for (int f = 0; f < 8; f++) bp[f] = 0.f;

            // uniform cubic B-spline, knots t_i = -2.2 + 0.4*i ; s = 2.5v + 5.5
            const float s  = fmaf(v, 2.5f, 5.5f);
            const float fj = floorf(s);
            const int   j  = (int)fj;
            if (j >= 0 && j <= 10) {
                const float u   = s - fj;
                const float u2  = u * u;
                const float u3  = u2 * u;
                const float omu = 1.f - u;
                const float w0 = omu * omu * omu * (1.f / 6.f);
                const float w1 = (3.f * u3 - 6.f * u2 + 4.f) * (1.f / 6.f);
                const float w2 = (-3.f * u3 + 3.f * u2 + 3.f * u + 1.f) * (1.f / 6.f);
                const float w3 = u3 * (1.f / 6.f);
                const int i0 = j - 3;               // nonzero bases i0..i0+3, clip to [0,7]
                if (i0 >= 0)             bp[i0]     = w0;
                if (i0 >= -1 && i0 <= 6) bp[i0 + 1] = w1;
                if (i0 >= -2 && i0 <= 5) bp[i0 + 2] = w2;
                if (i0 <= 4)             bp[i0 + 3] = w3;
            }
        }

        // ---- stage weights for this input channel: contiguous vec4 copy ----
        {
            const float4* src = (const float4*)&g_ws[c * (9 * 8 * OUT_C)];
            float4*       dst = (float4*)s_ws;
            #pragma unroll
            for (int l = 0; l < 9; l++)
                dst[l * 128 + tid] = src[l * 128 + tid];

            const float4* srcb = (const float4*)&g_wb[c * (9 * OUT_C)];
            float4*       dstb = (float4*)s_wb;
            dstb[tid] = srcb[tid];
            if (tid < 16) dstb[128 + tid] = srcb[128 + tid];
        }
        __syncthreads();

        // ---- accumulate over the 3x3 taps ----
        #pragma unroll 1
        for (int kh = 0; kh < 3; ++kh) {
            #pragma unroll 1
            for (int kw = 0; kw < 3; ++kw) {
                const int kk = kh * 3 + kw;

                // weights: [f][o] slice, float4 over o at this og (broadcast over pg)
                const float* wsk = &s_ws[kk * 8 * OUT_C];
                float4 wv4[8];
                #pragma unroll
                for (int f = 0; f < 8; f++)
                    wv4[f] = *(const float4*)&wsk[f * OUT_C + (og << 2)];
                const float* wvf = reinterpret_cast<const float*>(wv4);  // [f*4 + oi]
                const float4 wb4 = *(const float4*)&s_wb[kk * OUT_C + (og << 2)];
                const float* wbf = reinterpret_cast<const float*>(&wb4); // [oi]

                #pragma unroll
                for (int p = 0; p < TILE_H; p++) {
                    const int idx = (p + kh) * PADW + pg + kw;
                    const float xv = s_x[idx];
                    const float4 b0 = *(const float4*)&s_b[idx * BSTRIDE];
                    const float4 b1 = *(const float4*)&s_b[idx * BSTRIDE + 4];
                    const float bf[8] = { b0.x, b0.y, b0.z, b0.w,
                                          b1.x, b1.y, b1.z, b1.w };
                    #pragma unroll
                    for (int oi = 0; oi < 4; oi++) {
                        float t = accS[oi][p];
                        #pragma unroll
                        for (int f = 0; f < 8; f++)
                            t = fmaf(bf[f], wvf[f * 4 + oi], t);
                        accS[oi][p] = t;
                        accB[oi][p] = fmaf(xv, wbf[oi], accB[oi][p]);
                    }
                }
            }
        }
    }

    // ---- write raw partial sums (activation applied in combine) ----
    const int base = split * NOUT + b * (OUT_C * HH * WWID);
    #pragma unroll
    for (int oi = 0; oi < 4; oi++) {
        const int o = (og << 2) + oi;
        #pragma unroll
        for (int p = 0; p < TILE_H; p++) {
            const int idx = base + (o * HH + th0 + p) * WWID + tw0 + pg;
            g_partS[idx] = accS[oi][p];
            g_partB[idx] = accB[oi][p];
        }
    }
}

__global__ __launch_bounds__(256)
void kan_combine_kernel(const float* __restrict__ scaler, float* __restrict__ out)
{
    const int v = blockIdx.x * blockDim.x + threadIdx.x;   // float4 index
    if (v >= NOUT / 4) return;
    const int o = ((v * 4) / (HH * WWID)) & (OUT_C - 1);   // constant within a float4
    const float4 s0 = ((const float4*)g_partS)[v];
    const float4 s1 = ((const float4*)g_partS)[v + NOUT / 4];
    const float4 s2 = ((const float4*)g_partS)[v + 2 * (NOUT / 4)];
    const float4 b0 = ((const float4*)g_partB)[v];
    const float4 b1 = ((const float4*)g_partB)[v + NOUT / 4];
    const float4 b2 = ((const float4*)g_partB)[v + 2 * (NOUT / 4)];
    const float sc = scaler[o];
    float4 r;
    { const float zb = b0.x + b1.x + b2.x; r.x = fmaf(sc, s0.x + s1.x + s2.x, zb / (1.f + expf(-zb))); }
    { const float zb = b0.y + b1.y + b2.y; r.y = fmaf(sc, s0.y + s1.y + s2.y, zb / (1.f + expf(-zb))); }
    { const float zb = b0.z + b1.z + b2.z; r.z = fmaf(sc, s0.z + s1.z + s2.z, zb / (1.f + expf(-zb))); }
    { const float zb = b0.w + b1.w + b2.w; r.w = fmaf(sc, s0.w + s1.w + s2.w, zb / (1.f + expf(-zb))); }
    ((float4*)out)[v] = r;
}

extern "C" void kernel_launch(void* const* d_in, const int* in_sizes, int n_in,
                              void* d_out, int out_size)
{
    const float* x      = (const float*)d_in[0];
    const float* wb     = (const float*)d_in[1];
    const float* ws     = (const float*)d_in[2];
    const float* scaler = (const float*)d_in[3];
    float* out = (float*)d_out;

    kan_reorg_kernel<<<(OUT_C * IN_C * 9 + 255) / 256, 256>>>(ws, wb);

    dim3 grid(WWID / TILE_W, HH / TILE_H, BB * NSPLIT);   // (7, 7, 12) = 588 blocks
    kan_partial_kernel<<<grid, 128>>>(x);

    kan_combine_kernel<<<(NOUT / 4 + 255) / 256, 256>>>(scaler, out);
}

// round 16
// speedup vs baseline: 2.9461x; 1.8812x over previous
#include <cuda_runtime.h>
#include <math.h>
#include <stdint.h>

#define IN_C   32
#define OUT_C  64
#define HH     56
#define WWID   56
#define BB     4
#define PH     58              // padded plane dim
#define PSZ    (PH * PH)       // 3364
#define NPL    288             // 256 basis planes + 32 x planes
#define NCHUNK 36              // 32 spline (per input channel) + 4 base (8 ch each)
#define HALO_STRIDE 104        // smem floats per plane (10x10 rows of 10, padded)
#define BCHUNK_U2 2304         // 9 ks * 8 nt * 32 lanes uint2 per chunk

// Device scratch (no allocation).
__device__ float g_planes[BB * NPL * PSZ];              // 15.5 MB padded planes (tf32-rounded)
__device__ uint2 g_bpack[NCHUNK * BCHUNK_U2];           // weights in MMA-fragment lane order

__device__ __forceinline__ float tf32r(float f) {
    float r; asm("cvt.rna.tf32.f32 %0, %1;" : "=f"(r) : "f"(f)); return r;
}

__device__ __forceinline__ void mma_tf32(float& d0, float& d1, float& d2, float& d3,
                                         unsigned a0, unsigned a1, unsigned a2, unsigned a3,
                                         unsigned b0, unsigned b1) {
    asm volatile("mma.sync.aligned.m16n8k8.row.col.f32.tf32.tf32.f32 "
                 "{%0,%1,%2,%3}, {%4,%5,%6,%7}, {%8,%9}, {%0,%1,%2,%3};"
                 : "+f"(d0), "+f"(d1), "+f"(d2), "+f"(d3)
                 : "r"(a0), "r"(a1), "r"(a2), "r"(a3), "r"(b0), "r"(b1));
}

__device__ __forceinline__ uint32_t s2u(const void* p) {
    return (uint32_t)__cvta_generic_to_shared(p);
}
__device__ __forceinline__ void cpa4(uint32_t dst, const void* src) {
    asm volatile("cp.async.ca.shared.global [%0], [%1], 4;" :: "r"(dst), "l"(src));
}
__device__ __forceinline__ void cpa16(uint32_t dst, const void* src) {
    asm volatile("cp.async.cg.shared.global [%0], [%1], 16;" :: "r"(dst), "l"(src));
}

// ---- closed-form uniform cubic B-spline bases (verified vs Cox-de Boor) ----
__device__ __forceinline__ void bases8(float v, float* bp) {
    #pragma unroll
    for (int f = 0; f < 8; f++) bp[f] = 0.f;
    const float s  = fmaf(v, 2.5f, 5.5f);
    const float fj = floorf(s);
    const int   j  = (int)fj;
    if (j >= 0 && j <= 10) {
        const float u   = s - fj;
        const float u2  = u * u;
        const float u3  = u2 * u;
        const float omu = 1.f - u;
        const float w0 = omu * omu * omu * (1.f / 6.f);
        const float w1 = (3.f * u3 - 6.f * u2 + 4.f) * (1.f / 6.f);
        const float w2 = (-3.f * u3 + 3.f * u2 + 3.f * u + 1.f) * (1.f / 6.f);
        const float w3 = u3 * (1.f / 6.f);
        const int i0 = j - 3;
        if (i0 >= 0)             bp[i0]     = w0;
        if (i0 >= -1 && i0 <= 6) bp[i0 + 1] = w1;
        if (i0 >= -2 && i0 <= 5) bp[i0 + 2] = w2;
        if (i0 <= 4)             bp[i0 + 3] = w3;
    }
}

// ---- kernel 1: expand x into 288 padded planes (zero-extension BEFORE bases) ----
__global__ __launch_bounds__(256)
void kan_prep_kernel(const float* __restrict__ x)
{
    const int bc = blockIdx.y;            // b*32 + c
    const int b  = bc >> 5;
    const int c  = bc & 31;
    const int pp = blockIdx.x * 256 + threadIdx.x;
    if (pp >= PSZ) return;
    const int ph = pp / PH;
    const int pw = pp - ph * PH;
    const int gh = ph - 1, gw = pw - 1;
    float v = 0.f;
    if (gh >= 0 && gh < HH && gw >= 0 && gw < WWID)
        v = x[((bc) * HH + gh) * WWID + gw];

    float bp[8];
    bases8(v, bp);
    #pragma unroll
    for (int f = 0; f < 8; f++)
        g_planes[((b * NPL) + (c * 8 + f)) * PSZ + pp] = tf32r(bp[f]);
    g_planes[((b * NPL) + 256 + c) * PSZ + pp] = tf32r(v);
}

// ---- kernel 2: pack weights into per-lane MMA-fragment order ----
// Bpack[((ch*9 + kk)*8 + nt)*32 + lane] = { lo: W[k=i], hi: W[k=i+4] } for o = nt*8 + (lane>>2)
__global__ __launch_bounds__(256)
void kan_reorg_kernel(const float* __restrict__ ws, const float* __restrict__ wb)
{
    const int idx = blockIdx.x * blockDim.x + threadIdx.x;
    if (idx >= NCHUNK * BCHUNK_U2) return;
    const int ch   = idx / BCHUNK_U2;
    const int r    = idx - ch * BCHUNK_U2;
    const int kk   = r / 256;
    const int r2   = r - kk * 256;
    const int nt   = r2 >> 5;
    const int lane = r2 & 31;
    const int i = lane & 3;
    const int o = nt * 8 + (lane >> 2);

    float lo, hi;
    if (ch < 32) {          // spline chunk = input channel ch, k rows = f
        const int boff = o * 2304 + (ch * 9 + kk) * 8;
        lo = ws[boff + i];
        hi = ws[boff + i + 4];
    } else {                // base chunk: 8 x-channels, k rows = channel offset
        const int cb0 = (ch - 32) * 8;
        lo = wb[o * 288 + (cb0 + i) * 9 + kk];
        hi = wb[o * 288 + (cb0 + i + 4) * 9 + kk];
    }
    uint2 v;
    v.x = __float_as_uint(tf32r(lo));
    v.y = __float_as_uint(tf32r(hi));
    g_bpack[idx] = v;
}

// ---- kernel 3: main tensor-core conv ----
__global__ __launch_bounds__(128)
void kan_main_kernel(const float* __restrict__ scaler, float* __restrict__ out)
{
    __shared__ __align__(16) float s_h[2][8 * HALO_STRIDE];   // halo planes
    __shared__ __align__(16) uint2 s_bp[2][BCHUNK_U2];        // weight fragments

    const int tid  = threadIdx.x;
    const int wid  = tid >> 5;
    const int lane = tid & 31;
    const int tw0  = blockIdx.x * 8;
    const int th0  = blockIdx.y * 8;
    const int b    = blockIdx.z;

    float accS[8][4];
    float accB[8][4];
    #pragma unroll
    for (int nt = 0; nt < 8; nt++)
        #pragma unroll
        for (int k = 0; k < 4; k++) { accS[nt][k] = 0.f; accB[nt][k] = 0.f; }

    const float* plbase = g_planes + (size_t)b * NPL * PSZ;

    // A halo staging: 8 planes x 100 elements
    auto stageA = [&](int buf, int ch) {
        const int q0 = (ch < 32) ? ch * 8 : 256 + (ch - 32) * 8;
        const float* pb = plbase + (size_t)q0 * PSZ;
        #pragma unroll
        for (int it = 0; it < 7; ++it) {
            const int e = tid + it * 128;
            if (e < 800) {
                const int pl  = e / 100;
                const int pos = e - pl * 100;
                const int hh  = pos / 10;
                const int ww  = pos - hh * 10;
                cpa4(s2u(&s_h[buf][pl * HALO_STRIDE + pos]),
                     pb + pl * PSZ + (th0 + hh) * PH + (tw0 + ww));
            }
        }
    };
    auto stageB = [&](int buf, int ch) {
        const uint2* src = g_bpack + ch * BCHUNK_U2;
        #pragma unroll
        for (int it = 0; it < 9; ++it) {
            const int e = tid + it * 128;   // 1152 x 16B
            cpa16(s2u(&s_bp[buf][e * 2]), src + e * 2);
        }
    };

    const int aBase = (lane & 3) * HALO_STRIDE + wid * 20 + (lane >> 2);

#define COMPUTE(ACC, CB) do {                                                  \
    const float* hp = s_h[CB];                                                 \
    const uint2* bp = s_bp[CB];                                                \
    _Pragma("unroll")                                                          \
    for (int ks = 0; ks < 9; ++ks) {                                           \
        const int kh = ks / 3, kw = ks - kh * 3;                               \
        const int ai = aBase + kh * 10 + kw;                                   \
        const unsigned a0 = __float_as_uint(hp[ai]);                           \
        const unsigned a1 = __float_as_uint(hp[ai + 10]);                      \
        const unsigned a2 = __float_as_uint(hp[ai + 4 * HALO_STRIDE]);         \
        const unsigned a3 = __float_as_uint(hp[ai + 4 * HALO_STRIDE + 10]);    \
        _Pragma("unroll")                                                      \
        for (int nt = 0; nt < 8; ++nt) {                                       \
            const uint2 bv = bp[(ks * 8 + nt) * 32 + lane];                    \
            mma_tf32(ACC[nt][0], ACC[nt][1], ACC[nt][2], ACC[nt][3],           \
                     a0, a1, a2, a3, bv.x, bv.y);                              \
        }                                                                      \
    } } while (0)

    stageA(0, 0); stageB(0, 0);
    asm volatile("cp.async.commit_group;");

    #pragma unroll 1
    for (int ch = 0; ch < NCHUNK; ++ch) {
        if (ch + 1 < NCHUNK) {
            const int nb = (ch + 1) & 1;
            stageA(nb, ch + 1); stageB(nb, ch + 1);
        }
        asm volatile("cp.async.commit_group;");
        asm volatile("cp.async.wait_group 1;");
        __syncthreads();
        const int cb = ch & 1;
        if (ch < 32) COMPUTE(accS, cb);
        else         COMPUTE(accB, cb);
        __syncthreads();
    }
#undef COMPUTE

    // ---- epilogue: silu(base) + scaler * spline ----
    const int t = lane & 3;
    const int g = lane >> 2;
    const int w = tw0 + g;
    #pragma unroll
    for (int nt = 0; nt < 8; ++nt) {
        const int oc0 = nt * 8 + 2 * t;
        const float sc0 = __ldg(&scaler[oc0]);
        const float sc1 = __ldg(&scaler[oc0 + 1]);
        #pragma unroll
        for (int dh = 0; dh < 2; ++dh) {
            const int h = th0 + wid * 2 + dh;
            const float zb0 = accB[nt][dh * 2 + 0];
            const float zb1 = accB[nt][dh * 2 + 1];
            out[((b * OUT_C + oc0    ) * HH + h) * WWID + w] =
                fmaf(sc0, accS[nt][dh * 2 + 0], zb0 / (1.f + expf(-zb0)));
            out[((b * OUT_C + oc0 + 1) * HH + h) * WWID + w] =
                fmaf(sc1, accS[nt][dh * 2 + 1], zb1 / (1.f + expf(-zb1)));
        }
    }
}

extern "C" void kernel_launch(void* const* d_in, const int* in_sizes, int n_in,
                              void* d_out, int out_size)
{
    const float* x      = (const float*)d_in[0];
    const float* wb     = (const float*)d_in[1];
    const float* ws     = (const float*)d_in[2];
    const float* scaler = (const float*)d_in[3];
    float* out = (float*)d_out;

    dim3 gp((PSZ + 255) / 256, BB * IN_C);                 // (14, 128)
    kan_prep_kernel<<<gp, 256>>>(x);

    kan_reorg_kernel<<<(NCHUNK * BCHUNK_U2 + 255) / 256, 256>>>(ws, wb);

    dim3 gm(WWID / 8, HH / 8, BB);                         // (7, 7, 4) = 196 blocks
    kan_main_kernel<<<gm, 128>>>(scaler, out);
}